// round 1
// baseline (speedup 1.0000x reference)
#include <cuda_runtime.h>
#include <cstdint>

#define CB 4
#define CT 2048
#define CC 512
#define CH 8
#define CD 64
#define SCALE 0.044194173824159216f  // 1/sqrt(512)

// Scratch (64 MB): q, k, v, attention output, all laid out [B][H][T][D]
__device__ float g_q[CB*CH*CT*CD];
__device__ float g_k[CB*CH*CT*CD];
__device__ float g_v[CB*CH*CT*CD];
__device__ float g_ao[CB*CH*CT*CD];

// ---------------------------------------------------------------------------
// Kernel 1: fused QKV projection.
// grid (M/128=64, H=8, 3[q,k,v]); block 256.
// out[(b,h,t,d)] = sum_c X[b,t,c] * W[h,c,d]
// ---------------------------------------------------------------------------
__global__ __launch_bounds__(256) void qkv_kernel(
    const float* __restrict__ X,
    const float* __restrict__ Wq,
    const float* __restrict__ Wk,
    const float* __restrict__ Wv)
{
    __shared__ float As[32*132];   // [k][m] transposed A tile, pad 132
    __shared__ float Bs[32*68];    // [k][d] weight tile, pad 68

    const int m0 = blockIdx.x * 128;
    const int h  = blockIdx.y;
    const int z  = blockIdx.z;
    const float* W  = (z == 0) ? Wq : ((z == 1) ? Wk : Wv);
    float* Out      = (z == 0) ? g_q : ((z == 1) ? g_k : g_v);
    const float* Wh = W + h * CC * CD;

    const int tid = threadIdx.x;
    const int ty = tid >> 4, tx = tid & 15;
    const int ty8 = ty * 8, tx4 = tx * 4;

    float acc[8][4];
    #pragma unroll
    for (int i = 0; i < 8; i++)
        #pragma unroll
        for (int j = 0; j < 4; j++) acc[i][j] = 0.f;

    for (int kt = 0; kt < 16; kt++) {
        const int k0 = kt * 32;
        // Load A tile (X[m0..m0+127, k0..k0+31]) transposed into As[k][m]
        #pragma unroll
        for (int i = 0; i < 4; i++) {
            int f = tid + i * 256;       // 1024 float4
            int m = f >> 3, c4 = f & 7;
            float4 v = *(const float4*)(X + (m0 + m) * CC + k0 + c4 * 4);
            float vv[4] = {v.x, v.y, v.z, v.w};
            #pragma unroll
            for (int jj = 0; jj < 4; jj++) {
                int j = (jj + tid) & 3;   // stagger to reduce bank conflicts
                As[(c4 * 4 + j) * 132 + m] = vv[j];
            }
        }
        // Load B tile (Wh[k0..k0+31, 0..63]) natural layout Bs[k][d]
        #pragma unroll
        for (int i = 0; i < 2; i++) {
            int f = tid + i * 256;       // 512 float4
            int k = f >> 4, d4 = f & 15;
            *(float4*)&Bs[k * 68 + d4 * 4] =
                *(const float4*)(Wh + (k0 + k) * CD + d4 * 4);
        }
        __syncthreads();
        #pragma unroll 8
        for (int k = 0; k < 32; k++) {
            float4 a0 = *(float4*)&As[k * 132 + ty8];
            float4 a1 = *(float4*)&As[k * 132 + ty8 + 4];
            float4 b  = *(float4*)&Bs[k * 68 + tx4];
            float av[8] = {a0.x, a0.y, a0.z, a0.w, a1.x, a1.y, a1.z, a1.w};
            float bv[4] = {b.x, b.y, b.z, b.w};
            #pragma unroll
            for (int i = 0; i < 8; i++)
                #pragma unroll
                for (int j = 0; j < 4; j++)
                    acc[i][j] += av[i] * bv[j];
        }
        __syncthreads();
    }
    // Write out to [b][h][t][d]
    #pragma unroll
    for (int i = 0; i < 8; i++) {
        int r = m0 + ty8 + i;
        int bb = r >> 11, t = r & 2047;
        float4 st = make_float4(acc[i][0], acc[i][1], acc[i][2], acc[i][3]);
        *(float4*)(Out + ((bb * CH + h) * CT + t) * CD + tx4) = st;
    }
}

// ---------------------------------------------------------------------------
// Kernel 2: flash attention with fused relative-position scores.
// grid (32 t-blocks [descending], H, B); block 256.
// Per s-tile: one GEMM Q[64x64] x [K-tile(64) ++ rel-window(127)]^T -> 64x192,
// then score[t][s] = AC[t][s] + QR[t][63 + s - t], causal+global mask,
// online softmax, PV accumulate.
// ---------------------------------------------------------------------------
__global__ __launch_bounds__(256, 2) void attn_kernel(const float* __restrict__ rel)
{
    extern __shared__ float smf[];
    float* Qs  = smf;               // [64][68]  layout [d][t]
    float* KRs = smf + 64 * 68;     // [64][196] layout [d][n]; reused as S2s [t][196]
    float* Vs  = KRs + 64 * 196;    // [64][68]  layout [s][d]
    float* Ps  = Vs + 64 * 68;      // [64][68]  layout [s][t]

    const int tb = 31 - blockIdx.x;  // big blocks first (tail balance)
    const int h  = blockIdx.y;
    const int b  = blockIdx.z;
    const int t0 = tb * 64;
    const int tid = threadIdx.x;
    const int ty = tid >> 4, tx = tid & 15;
    const int ty4 = ty * 4, tx4 = tx * 4;

    const int bh = b * CH + h;
    const float* qg   = g_q + ((size_t)bh * CT + t0) * CD;
    const float* relh = rel + (size_t)h * CT * CD;

    // Load Q transposed into Qs[d][t]
    #pragma unroll
    for (int i = 0; i < 4; i++) {
        int f = tid + i * 256;
        int t = f >> 4, d4 = f & 15;
        float4 v = *(const float4*)(qg + t * CD + d4 * 4);
        float vv[4] = {v.x, v.y, v.z, v.w};
        #pragma unroll
        for (int jj = 0; jj < 4; jj++) {
            int j = (jj + tid) & 3;
            Qs[(d4 * 4 + j) * 68 + t] = vv[j];
        }
    }

    float o[4][4];
    #pragma unroll
    for (int i = 0; i < 4; i++)
        #pragma unroll
        for (int j = 0; j < 4; j++) o[i][j] = 0.f;
    float mrow[4] = {-1e30f, -1e30f, -1e30f, -1e30f};
    float lrow[4] = {0.f, 0.f, 0.f, 0.f};

    for (int st = 0; st <= tb; st++) {
        const int s0 = st * 64;
        const float* kg = g_k + ((size_t)bh * CT + s0) * CD;
        const float* vg = g_v + ((size_t)bh * CT + s0) * CD;
        __syncthreads();  // previous iteration's smem reads complete

        // K tile transposed into KRs[d][0..63]
        #pragma unroll
        for (int i = 0; i < 4; i++) {
            int f = tid + i * 256;
            int s = f >> 4, d4 = f & 15;
            float4 v = *(const float4*)(kg + s * CD + d4 * 4);
            float vv[4] = {v.x, v.y, v.z, v.w};
            #pragma unroll
            for (int jj = 0; jj < 4; jj++) {
                int j = (jj + tid) & 3;
                KRs[(d4 * 4 + j) * 196 + s] = vv[j];
            }
        }
        // rel window (127 rows) into KRs[d][64..190]; row j0+w, w in [0,126]
        const int j0 = 1984 - (t0 - s0);   // = T-1 + s0 - t0 - 63, always >= 0
        #pragma unroll
        for (int i = 0; i < 8; i++) {
            int f = tid + i * 256;
            if (f < 2032) {                 // 127*64/4 float4
                int w = f >> 4, d4 = f & 15;
                int jr = j0 + w;
                float4 v = make_float4(0.f, 0.f, 0.f, 0.f);
                if (jr < CT) v = *(const float4*)(relh + jr * CD + d4 * 4);
                float vv[4] = {v.x, v.y, v.z, v.w};
                #pragma unroll
                for (int jj = 0; jj < 4; jj++) {
                    int j = (jj + tid) & 3;
                    KRs[(d4 * 4 + j) * 196 + 64 + w] = vv[j];
                }
            }
        }
        if (tid < 64) KRs[tid * 196 + 191] = 0.f;  // pad col read by GEMM
        // V tile natural layout Vs[s][d]
        #pragma unroll
        for (int i = 0; i < 4; i++) {
            int f = tid + i * 256;
            int s = f >> 4, d4 = f & 15;
            *(float4*)&Vs[s * 68 + d4 * 4] =
                *(const float4*)(vg + s * CD + d4 * 4);
        }
        __syncthreads();

        // GEMM1: S2[t][n] = sum_d Q[t][d] * KR[n][d], n in [0,192)
        float acc2[3][4][4];
        #pragma unroll
        for (int c = 0; c < 3; c++)
            #pragma unroll
            for (int i = 0; i < 4; i++)
                #pragma unroll
                for (int j = 0; j < 4; j++) acc2[c][i][j] = 0.f;
        #pragma unroll 4
        for (int d = 0; d < 64; d++) {
            float4 aq = *(float4*)&Qs[d * 68 + ty4];
            float a4[4] = {aq.x, aq.y, aq.z, aq.w};
            #pragma unroll
            for (int c = 0; c < 3; c++) {
                float4 bb4 = *(float4*)&KRs[d * 196 + c * 64 + tx4];
                float b4[4] = {bb4.x, bb4.y, bb4.z, bb4.w};
                #pragma unroll
                for (int i = 0; i < 4; i++)
                    #pragma unroll
                    for (int j = 0; j < 4; j++)
                        acc2[c][i][j] += a4[i] * b4[j];
            }
        }
        __syncthreads();
        // Dump S2 into smem (reuse KRs region), layout [t][196]
        float* S2s = KRs;
        #pragma unroll
        for (int c = 0; c < 3; c++)
            #pragma unroll
            for (int i = 0; i < 4; i++) {
                float4 stv = make_float4(acc2[c][i][0], acc2[c][i][1],
                                         acc2[c][i][2], acc2[c][i][3]);
                *(float4*)&S2s[(ty4 + i) * 196 + c * 64 + tx4] = stv;
            }
        __syncthreads();

        // Gather scores, mask, online softmax
        float sc[4][4];
        #pragma unroll
        for (int i = 0; i < 4; i++) {
            const int tl = ty4 + i, tg = t0 + tl;
            #pragma unroll
            for (int j = 0; j < 4; j++) {
                const int sl = tx4 + j, sg = s0 + sl;
                float ac = S2s[tl * 196 + sl];
                float bd = S2s[tl * 196 + 64 + sl - tl + 63];
                float val;
                if (sg <= tg) {
                    val = (ac + bd) * SCALE;
                } else if (sg < 6) {
                    // rel_shift wrap for unmasked global cols above diagonal:
                    // 0 if sg==tg+1, else q[tg+1] . rel[sg-tg-2]
                    float bds = 0.f;
                    if (sg != tg + 1) {
                        int jr = sg - tg - 2;
                        const float* rp = relh + jr * CD;
                        float a = 0.f;
                        for (int d = 0; d < 64; d++)
                            a += Qs[d * 68 + tl + 1] * rp[d];
                        bds = a;
                    }
                    val = (ac + bds) * SCALE;
                } else {
                    val = -1e30f;
                }
                sc[i][j] = val;
            }
        }
        #pragma unroll
        for (int i = 0; i < 4; i++) {
            float tm = fmaxf(fmaxf(sc[i][0], sc[i][1]), fmaxf(sc[i][2], sc[i][3]));
            #pragma unroll
            for (int off = 8; off >= 1; off >>= 1)
                tm = fmaxf(tm, __shfl_xor_sync(0xffffffffu, tm, off));
            float nm = fmaxf(mrow[i], tm);
            float corr = __expf(mrow[i] - nm);
            float rs = 0.f;
            #pragma unroll
            for (int j = 0; j < 4; j++) {
                sc[i][j] = __expf(sc[i][j] - nm);
                rs += sc[i][j];
            }
            #pragma unroll
            for (int off = 8; off >= 1; off >>= 1)
                rs += __shfl_xor_sync(0xffffffffu, rs, off);
            lrow[i] = lrow[i] * corr + rs;
            mrow[i] = nm;
            #pragma unroll
            for (int j = 0; j < 4; j++) o[i][j] *= corr;
        }
        // Store P transposed [s][t]
        #pragma unroll
        for (int j = 0; j < 4; j++) {
            float4 pv = make_float4(sc[0][j], sc[1][j], sc[2][j], sc[3][j]);
            *(float4*)&Ps[(tx4 + j) * 68 + ty4] = pv;
        }
        __syncthreads();
        // PV: o[t][d] += sum_s P[t][s] * V[s][d]
        #pragma unroll 4
        for (int s = 0; s < 64; s++) {
            float4 ap = *(float4*)&Ps[s * 68 + ty4];
            float4 bv = *(float4*)&Vs[s * 68 + tx4];
            float a4[4] = {ap.x, ap.y, ap.z, ap.w};
            float b4[4] = {bv.x, bv.y, bv.z, bv.w};
            #pragma unroll
            for (int i = 0; i < 4; i++)
                #pragma unroll
                for (int j = 0; j < 4; j++)
                    o[i][j] += a4[i] * b4[j];
        }
    }

    // Normalize and write out [b][h][t][d]
    float* og = g_ao + ((size_t)bh * CT + t0) * CD;
    #pragma unroll
    for (int i = 0; i < 4; i++) {
        float inv = 1.f / lrow[i];
        float4 stv = make_float4(o[i][0] * inv, o[i][1] * inv,
                                 o[i][2] * inv, o[i][3] * inv);
        *(float4*)(og + (ty4 + i) * CD + tx4) = stv;
    }
}

// ---------------------------------------------------------------------------
// Kernel 3: output projection. out[b,t,:] = concat_heads(ao) @ Wp + bp
// grid (64 m-tiles, 8 n-tiles); block 256.
// ---------------------------------------------------------------------------
__global__ __launch_bounds__(256) void proj_kernel(
    const float* __restrict__ Wp,
    const float* __restrict__ bp,
    float* __restrict__ Out)
{
    __shared__ float As[32*132];
    __shared__ float Bs[32*68];

    const int m0 = blockIdx.x * 128;
    const int n0 = blockIdx.y * 64;
    const int tid = threadIdx.x;
    const int ty = tid >> 4, tx = tid & 15;
    const int ty8 = ty * 8, tx4 = tx * 4;

    float acc[8][4];
    #pragma unroll
    for (int i = 0; i < 8; i++)
        #pragma unroll
        for (int j = 0; j < 4; j++) acc[i][j] = 0.f;

    for (int kt = 0; kt < 16; kt++) {
        const int k0 = kt * 32;
        const int head = k0 >> 6;
        const int dk = k0 & 63;
        // A tile from g_ao with head-concat column mapping
        #pragma unroll
        for (int i = 0; i < 4; i++) {
            int f = tid + i * 256;
            int m = f >> 3, c4 = f & 7;
            int r = m0 + m;
            int bb = r >> 11, t = r & 2047;
            float4 v = *(const float4*)(g_ao +
                ((bb * CH + head) * CT + t) * CD + dk + c4 * 4);
            float vv[4] = {v.x, v.y, v.z, v.w};
            #pragma unroll
            for (int jj = 0; jj < 4; jj++) {
                int j = (jj + tid) & 3;
                As[(c4 * 4 + j) * 132 + m] = vv[j];
            }
        }
        #pragma unroll
        for (int i = 0; i < 2; i++) {
            int f = tid + i * 256;
            int k = f >> 4, d4 = f & 15;
            *(float4*)&Bs[k * 68 + d4 * 4] =
                *(const float4*)(Wp + (k0 + k) * CC + n0 + d4 * 4);
        }
        __syncthreads();
        #pragma unroll 8
        for (int k = 0; k < 32; k++) {
            float4 a0 = *(float4*)&As[k * 132 + ty8];
            float4 a1 = *(float4*)&As[k * 132 + ty8 + 4];
            float4 b  = *(float4*)&Bs[k * 68 + tx4];
            float av[8] = {a0.x, a0.y, a0.z, a0.w, a1.x, a1.y, a1.z, a1.w};
            float bv[4] = {b.x, b.y, b.z, b.w};
            #pragma unroll
            for (int i = 0; i < 8; i++)
                #pragma unroll
                for (int j = 0; j < 4; j++)
                    acc[i][j] += av[i] * bv[j];
        }
        __syncthreads();
    }
    float4 bias = *(const float4*)(bp + n0 + tx4);
    float bv[4] = {bias.x, bias.y, bias.z, bias.w};
    #pragma unroll
    for (int i = 0; i < 8; i++) {
        int r = m0 + ty8 + i;
        float4 stv = make_float4(acc[i][0] + bv[0], acc[i][1] + bv[1],
                                 acc[i][2] + bv[2], acc[i][3] + bv[3]);
        *(float4*)(Out + (size_t)r * CC + n0 + tx4) = stv;
    }
}

// ---------------------------------------------------------------------------
extern "C" void kernel_launch(void* const* d_in, const int* in_sizes, int n_in,
                              void* d_out, int out_size)
{
    const float* x   = (const float*)d_in[0];
    const float* Wq  = (const float*)d_in[1];
    const float* Wk  = (const float*)d_in[2];
    const float* Wv  = (const float*)d_in[3];
    const float* rel = (const float*)d_in[4];
    const float* Wp  = (const float*)d_in[5];
    const float* bp  = (const float*)d_in[6];
    float* out = (float*)d_out;

    (void)in_sizes; (void)n_in; (void)out_size;

    const int attn_smem = 64 * 68 * 4 + 64 * 196 * 4 + 64 * 68 * 4 + 64 * 68 * 4; // 102400 B
    cudaFuncSetAttribute(attn_kernel,
                         cudaFuncAttributeMaxDynamicSharedMemorySize, attn_smem);

    qkv_kernel<<<dim3(64, 8, 3), 256>>>(x, Wq, Wk, Wv);
    attn_kernel<<<dim3(32, 8, 4), 256, attn_smem>>>(rel);
    proj_kernel<<<dim3(64, 8), 256>>>(Wp, bp, out);
}

// round 2
// speedup vs baseline: 1.0150x; 1.0150x over previous
#include <cuda_runtime.h>
#include <cstdint>

#define CB 4
#define CT 2048
#define CC 512
#define CH 8
#define CD 64
#define SCALE 0.044194173824159216f  // 1/sqrt(512)

// Scratch (64 MB): q, k, v, attention output, all laid out [B][H][T][D]
__device__ float g_q[CB*CH*CT*CD];
__device__ float g_k[CB*CH*CT*CD];
__device__ float g_v[CB*CH*CT*CD];
__device__ float g_ao[CB*CH*CT*CD];

// ---------------------------------------------------------------------------
// Kernel 1: fused QKV projection.
// grid (M/128=64, H=8, 3[q,k,v]); block 256.
// out[(b,h,t,d)] = sum_c X[b,t,c] * W[h,c,d]
// ---------------------------------------------------------------------------
__global__ __launch_bounds__(256) void qkv_kernel(
    const float* __restrict__ X,
    const float* __restrict__ Wq,
    const float* __restrict__ Wk,
    const float* __restrict__ Wv)
{
    __shared__ float As[32*132];   // [k][m] transposed A tile, pad 132
    __shared__ float Bs[32*68];    // [k][d] weight tile, pad 68

    const int m0 = blockIdx.x * 128;
    const int h  = blockIdx.y;
    const int z  = blockIdx.z;
    const float* W  = (z == 0) ? Wq : ((z == 1) ? Wk : Wv);
    float* Out      = (z == 0) ? g_q : ((z == 1) ? g_k : g_v);
    const float* Wh = W + h * CC * CD;

    const int tid = threadIdx.x;
    const int ty = tid >> 4, tx = tid & 15;
    const int ty8 = ty * 8, tx4 = tx * 4;

    float acc[8][4];
    #pragma unroll
    for (int i = 0; i < 8; i++)
        #pragma unroll
        for (int j = 0; j < 4; j++) acc[i][j] = 0.f;

    for (int kt = 0; kt < 16; kt++) {
        const int k0 = kt * 32;
        // Load A tile (X[m0..m0+127, k0..k0+31]) transposed into As[k][m]
        #pragma unroll
        for (int i = 0; i < 4; i++) {
            int f = tid + i * 256;       // 1024 float4
            int m = f >> 3, c4 = f & 7;
            float4 v = *(const float4*)(X + (m0 + m) * CC + k0 + c4 * 4);
            float vv[4] = {v.x, v.y, v.z, v.w};
            #pragma unroll
            for (int jj = 0; jj < 4; jj++) {
                int j = (jj + tid) & 3;   // stagger to reduce bank conflicts
                As[(c4 * 4 + j) * 132 + m] = vv[j];
            }
        }
        // Load B tile (Wh[k0..k0+31, 0..63]) natural layout Bs[k][d]
        #pragma unroll
        for (int i = 0; i < 2; i++) {
            int f = tid + i * 256;       // 512 float4
            int k = f >> 4, d4 = f & 15;
            *(float4*)&Bs[k * 68 + d4 * 4] =
                *(const float4*)(Wh + (k0 + k) * CD + d4 * 4);
        }
        __syncthreads();
        #pragma unroll 8
        for (int k = 0; k < 32; k++) {
            float4 a0 = *(float4*)&As[k * 132 + ty8];
            float4 a1 = *(float4*)&As[k * 132 + ty8 + 4];
            float4 b  = *(float4*)&Bs[k * 68 + tx4];
            float av[8] = {a0.x, a0.y, a0.z, a0.w, a1.x, a1.y, a1.z, a1.w};
            float bv[4] = {b.x, b.y, b.z, b.w};
            #pragma unroll
            for (int i = 0; i < 8; i++)
                #pragma unroll
                for (int j = 0; j < 4; j++)
                    acc[i][j] += av[i] * bv[j];
        }
        __syncthreads();
    }
    // Write out to [b][h][t][d]
    #pragma unroll
    for (int i = 0; i < 8; i++) {
        int r = m0 + ty8 + i;
        int bb = r >> 11, t = r & 2047;
        float4 st = make_float4(acc[i][0], acc[i][1], acc[i][2], acc[i][3]);
        *(float4*)(Out + ((bb * CH + h) * CT + t) * CD + tx4) = st;
    }
}

// ---------------------------------------------------------------------------
// Kernel 2: flash attention with fused relative-position scores.
// grid (32 t-blocks [descending], H, B); block 256.
// Per s-tile: one GEMM Q[64x64] x [K-tile(64) ++ rel-window(127)]^T -> 64x192,
// then score[t][s] = AC[t][s] + QR[t][63 + s - t], causal+global mask,
// online softmax, PV accumulate.
// ---------------------------------------------------------------------------
__global__ __launch_bounds__(256, 2) void attn_kernel(const float* __restrict__ rel)
{
    extern __shared__ float smf[];
    float* Qs  = smf;               // [64][68]  layout [d][t]
    float* KRs = smf + 64 * 68;     // [64][196] layout [d][n]; reused as S2s [t][196]
    float* Vs  = KRs + 64 * 196;    // [64][68]  layout [s][d]
    float* Ps  = Vs + 64 * 68;      // [64][68]  layout [s][t]

    const int tb = 31 - blockIdx.x;  // big blocks first (tail balance)
    const int h  = blockIdx.y;
    const int b  = blockIdx.z;
    const int t0 = tb * 64;
    const int tid = threadIdx.x;
    const int ty = tid >> 4, tx = tid & 15;
    const int ty4 = ty * 4, tx4 = tx * 4;

    const int bh = b * CH + h;
    const float* qg   = g_q + ((size_t)bh * CT + t0) * CD;
    const float* relh = rel + (size_t)h * CT * CD;

    // Load Q transposed into Qs[d][t]
    #pragma unroll
    for (int i = 0; i < 4; i++) {
        int f = tid + i * 256;
        int t = f >> 4, d4 = f & 15;
        float4 v = *(const float4*)(qg + t * CD + d4 * 4);
        float vv[4] = {v.x, v.y, v.z, v.w};
        #pragma unroll
        for (int jj = 0; jj < 4; jj++) {
            int j = (jj + tid) & 3;
            Qs[(d4 * 4 + j) * 68 + t] = vv[j];
        }
    }

    float o[4][4];
    #pragma unroll
    for (int i = 0; i < 4; i++)
        #pragma unroll
        for (int j = 0; j < 4; j++) o[i][j] = 0.f;
    float mrow[4] = {-1e30f, -1e30f, -1e30f, -1e30f};
    float lrow[4] = {0.f, 0.f, 0.f, 0.f};

    for (int st = 0; st <= tb; st++) {
        const int s0 = st * 64;
        const float* kg = g_k + ((size_t)bh * CT + s0) * CD;
        const float* vg = g_v + ((size_t)bh * CT + s0) * CD;
        __syncthreads();  // previous iteration's smem reads complete

        // K tile transposed into KRs[d][0..63]
        #pragma unroll
        for (int i = 0; i < 4; i++) {
            int f = tid + i * 256;
            int s = f >> 4, d4 = f & 15;
            float4 v = *(const float4*)(kg + s * CD + d4 * 4);
            float vv[4] = {v.x, v.y, v.z, v.w};
            #pragma unroll
            for (int jj = 0; jj < 4; jj++) {
                int j = (jj + tid) & 3;
                KRs[(d4 * 4 + j) * 196 + s] = vv[j];
            }
        }
        // rel window (127 rows) into KRs[d][64..190]; row j0+w, w in [0,126]
        const int j0 = 1984 - (t0 - s0);   // = T-1 + s0 - t0 - 63, always >= 0
        #pragma unroll
        for (int i = 0; i < 8; i++) {
            int f = tid + i * 256;
            if (f < 2032) {                 // 127*64/4 float4
                int w = f >> 4, d4 = f & 15;
                int jr = j0 + w;
                float4 v = make_float4(0.f, 0.f, 0.f, 0.f);
                if (jr < CT) v = *(const float4*)(relh + jr * CD + d4 * 4);
                float vv[4] = {v.x, v.y, v.z, v.w};
                #pragma unroll
                for (int jj = 0; jj < 4; jj++) {
                    int j = (jj + tid) & 3;
                    KRs[(d4 * 4 + j) * 196 + 64 + w] = vv[j];
                }
            }
        }
        if (tid < 64) KRs[tid * 196 + 191] = 0.f;  // pad col read by GEMM
        // V tile natural layout Vs[s][d]
        #pragma unroll
        for (int i = 0; i < 4; i++) {
            int f = tid + i * 256;
            int s = f >> 4, d4 = f & 15;
            *(float4*)&Vs[s * 68 + d4 * 4] =
                *(const float4*)(vg + s * CD + d4 * 4);
        }
        __syncthreads();

        // GEMM1: S2[t][n] = sum_d Q[t][d] * KR[n][d], n in [0,192)
        float acc2[3][4][4];
        #pragma unroll
        for (int c = 0; c < 3; c++)
            #pragma unroll
            for (int i = 0; i < 4; i++)
                #pragma unroll
                for (int j = 0; j < 4; j++) acc2[c][i][j] = 0.f;
        #pragma unroll 4
        for (int d = 0; d < 64; d++) {
            float4 aq = *(float4*)&Qs[d * 68 + ty4];
            float a4[4] = {aq.x, aq.y, aq.z, aq.w};
            #pragma unroll
            for (int c = 0; c < 3; c++) {
                float4 bb4 = *(float4*)&KRs[d * 196 + c * 64 + tx4];
                float b4[4] = {bb4.x, bb4.y, bb4.z, bb4.w};
                #pragma unroll
                for (int i = 0; i < 4; i++)
                    #pragma unroll
                    for (int j = 0; j < 4; j++)
                        acc2[c][i][j] += a4[i] * b4[j];
            }
        }
        __syncthreads();
        // Dump S2 into smem (reuse KRs region), layout [t][196]
        float* S2s = KRs;
        #pragma unroll
        for (int c = 0; c < 3; c++)
            #pragma unroll
            for (int i = 0; i < 4; i++) {
                float4 stv = make_float4(acc2[c][i][0], acc2[c][i][1],
                                         acc2[c][i][2], acc2[c][i][3]);
                *(float4*)&S2s[(ty4 + i) * 196 + c * 64 + tx4] = stv;
            }
        __syncthreads();

        // Gather scores, mask, online softmax
        float sc[4][4];
        #pragma unroll
        for (int i = 0; i < 4; i++) {
            const int tl = ty4 + i, tg = t0 + tl;
            #pragma unroll
            for (int j = 0; j < 4; j++) {
                const int sl = tx4 + j, sg = s0 + sl;
                float ac = S2s[tl * 196 + sl];
                float bd = S2s[tl * 196 + 64 + sl - tl + 63];
                float val;
                if (sg <= tg) {
                    val = (ac + bd) * SCALE;
                } else if (sg < 6) {
                    // rel_shift wrap for unmasked global cols above diagonal:
                    // 0 if sg==tg+1, else q[tg+1] . rel[sg-tg-2]
                    float bds = 0.f;
                    if (sg != tg + 1) {
                        int jr = sg - tg - 2;
                        const float* rp = relh + jr * CD;
                        float a = 0.f;
                        for (int d = 0; d < 64; d++)
                            a += Qs[d * 68 + tl + 1] * rp[d];
                        bds = a;
                    }
                    val = (ac + bds) * SCALE;
                } else {
                    val = -1e30f;
                }
                sc[i][j] = val;
            }
        }
        #pragma unroll
        for (int i = 0; i < 4; i++) {
            float tm = fmaxf(fmaxf(sc[i][0], sc[i][1]), fmaxf(sc[i][2], sc[i][3]));
            #pragma unroll
            for (int off = 8; off >= 1; off >>= 1)
                tm = fmaxf(tm, __shfl_xor_sync(0xffffffffu, tm, off));
            float nm = fmaxf(mrow[i], tm);
            float corr = __expf(mrow[i] - nm);
            float rs = 0.f;
            #pragma unroll
            for (int j = 0; j < 4; j++) {
                sc[i][j] = __expf(sc[i][j] - nm);
                rs += sc[i][j];
            }
            #pragma unroll
            for (int off = 8; off >= 1; off >>= 1)
                rs += __shfl_xor_sync(0xffffffffu, rs, off);
            lrow[i] = lrow[i] * corr + rs;
            mrow[i] = nm;
            #pragma unroll
            for (int j = 0; j < 4; j++) o[i][j] *= corr;
        }
        // Store P transposed [s][t]
        #pragma unroll
        for (int j = 0; j < 4; j++) {
            float4 pv = make_float4(sc[0][j], sc[1][j], sc[2][j], sc[3][j]);
            *(float4*)&Ps[(tx4 + j) * 68 + ty4] = pv;
        }
        __syncthreads();
        // PV: o[t][d] += sum_s P[t][s] * V[s][d]
        #pragma unroll 4
        for (int s = 0; s < 64; s++) {
            float4 ap = *(float4*)&Ps[s * 68 + ty4];
            float4 bv = *(float4*)&Vs[s * 68 + tx4];
            float a4[4] = {ap.x, ap.y, ap.z, ap.w};
            float b4[4] = {bv.x, bv.y, bv.z, bv.w};
            #pragma unroll
            for (int i = 0; i < 4; i++)
                #pragma unroll
                for (int j = 0; j < 4; j++)
                    o[i][j] += a4[i] * b4[j];
        }
    }

    // Normalize and write out [b][h][t][d]
    float* og = g_ao + ((size_t)bh * CT + t0) * CD;
    #pragma unroll
    for (int i = 0; i < 4; i++) {
        float inv = 1.f / lrow[i];
        float4 stv = make_float4(o[i][0] * inv, o[i][1] * inv,
                                 o[i][2] * inv, o[i][3] * inv);
        *(float4*)(og + (ty4 + i) * CD + tx4) = stv;
    }
}

// ---------------------------------------------------------------------------
// Kernel 3: output projection. out[b,t,:] = concat_heads(ao) @ Wp + bp
// grid (64 m-tiles, 8 n-tiles); block 256.
// ---------------------------------------------------------------------------
__global__ __launch_bounds__(256) void proj_kernel(
    const float* __restrict__ Wp,
    const float* __restrict__ bp,
    float* __restrict__ Out)
{
    __shared__ float As[32*132];
    __shared__ float Bs[32*68];

    const int m0 = blockIdx.x * 128;
    const int n0 = blockIdx.y * 64;
    const int tid = threadIdx.x;
    const int ty = tid >> 4, tx = tid & 15;
    const int ty8 = ty * 8, tx4 = tx * 4;

    float acc[8][4];
    #pragma unroll
    for (int i = 0; i < 8; i++)
        #pragma unroll
        for (int j = 0; j < 4; j++) acc[i][j] = 0.f;

    for (int kt = 0; kt < 16; kt++) {
        const int k0 = kt * 32;
        const int head = k0 >> 6;
        const int dk = k0 & 63;
        // A tile from g_ao with head-concat column mapping
        #pragma unroll
        for (int i = 0; i < 4; i++) {
            int f = tid + i * 256;
            int m = f >> 3, c4 = f & 7;
            int r = m0 + m;
            int bb = r >> 11, t = r & 2047;
            float4 v = *(const float4*)(g_ao +
                ((bb * CH + head) * CT + t) * CD + dk + c4 * 4);
            float vv[4] = {v.x, v.y, v.z, v.w};
            #pragma unroll
            for (int jj = 0; jj < 4; jj++) {
                int j = (jj + tid) & 3;
                As[(c4 * 4 + j) * 132 + m] = vv[j];
            }
        }
        #pragma unroll
        for (int i = 0; i < 2; i++) {
            int f = tid + i * 256;
            int k = f >> 4, d4 = f & 15;
            *(float4*)&Bs[k * 68 + d4 * 4] =
                *(const float4*)(Wp + (k0 + k) * CC + n0 + d4 * 4);
        }
        __syncthreads();
        #pragma unroll 8
        for (int k = 0; k < 32; k++) {
            float4 a0 = *(float4*)&As[k * 132 + ty8];
            float4 a1 = *(float4*)&As[k * 132 + ty8 + 4];
            float4 b  = *(float4*)&Bs[k * 68 + tx4];
            float av[8] = {a0.x, a0.y, a0.z, a0.w, a1.x, a1.y, a1.z, a1.w};
            float bv[4] = {b.x, b.y, b.z, b.w};
            #pragma unroll
            for (int i = 0; i < 8; i++)
                #pragma unroll
                for (int j = 0; j < 4; j++)
                    acc[i][j] += av[i] * bv[j];
        }
        __syncthreads();
    }
    float4 bias = *(const float4*)(bp + n0 + tx4);
    float bv[4] = {bias.x, bias.y, bias.z, bias.w};
    #pragma unroll
    for (int i = 0; i < 8; i++) {
        int r = m0 + ty8 + i;
        float4 stv = make_float4(acc[i][0] + bv[0], acc[i][1] + bv[1],
                                 acc[i][2] + bv[2], acc[i][3] + bv[3]);
        *(float4*)(Out + (size_t)r * CC + n0 + tx4) = stv;
    }
}

// ---------------------------------------------------------------------------
extern "C" void kernel_launch(void* const* d_in, const int* in_sizes, int n_in,
                              void* d_out, int out_size)
{
    const float* x   = (const float*)d_in[0];
    const float* Wq  = (const float*)d_in[1];
    const float* Wk  = (const float*)d_in[2];
    const float* Wv  = (const float*)d_in[3];
    const float* rel = (const float*)d_in[4];
    const float* Wp  = (const float*)d_in[5];
    const float* bp  = (const float*)d_in[6];
    float* out = (float*)d_out;

    (void)in_sizes; (void)n_in; (void)out_size;

    const int attn_smem = 64 * 68 * 4 + 64 * 196 * 4 + 64 * 68 * 4 + 64 * 68 * 4; // 102400 B
    cudaFuncSetAttribute(attn_kernel,
                         cudaFuncAttributeMaxDynamicSharedMemorySize, attn_smem);

    qkv_kernel<<<dim3(64, 8, 3), 256>>>(x, Wq, Wk, Wv);
    attn_kernel<<<dim3(32, 8, 4), 256, attn_smem>>>(rel);
    proj_kernel<<<dim3(64, 8), 256>>>(Wp, bp, out);
}